// round 3
// baseline (speedup 1.0000x reference)
#include <cuda_runtime.h>

// EdgeAugmentation, single-kernel formulation.
// LayerNorm over a singleton axis => every score == beta => stable top_k picks
// the first TOPK row-major (i,j) per graph that are neither an existing
// same-graph edge nor diagonal. Output buffer is float32.
//
// One block per graph: scan all edges, record own-graph edges in a 2KB smem
// bitmap, copy own 1/64 slice of edge_index to the output (float-converted)
// in the same pass, then rank-scan the free bitmap for the first 16 cells.

#define E_EDGES 65536
#define BQ      64
#define TOPK_K  16
#define AUG     (E_EDGES + BQ * TOPK_K)   // 66560 columns in aug_edge_index
#define WORDS   512                        // 128*128 bits / 32

__global__ void __launch_bounds__(512, 1)
fused_kernel(const int* __restrict__ ei, float* __restrict__ out, int write_count) {
    __shared__ unsigned bm[WORDS];
    __shared__ int wsum[16];

    const int b    = blockIdx.x;
    const int t    = threadIdx.x;         // 0..511
    const int boff = b << 7;              // b * Ng

    bm[t] = 0u;
    __syncthreads();

    const int4* s_in = (const int4*)ei;
    const int4* d_in = (const int4*)(ei + E_EDGES);

    // Scan all edges (4 per iteration); 32 iterations per thread.
    #pragma unroll 4
    for (int e4 = t; e4 < E_EDGES / 4; e4 += 512) {
        int4 s4 = s_in[e4];
        unsigned us0 = (unsigned)(s4.x - boff);
        unsigned us1 = (unsigned)(s4.y - boff);
        unsigned us2 = (unsigned)(s4.z - boff);
        unsigned us3 = (unsigned)(s4.w - boff);

        bool own    = (unsigned)(e4 - (b << 8)) < 256u;   // own copy slice
        bool anyhit = (us0 < 128u) | (us1 < 128u) | (us2 < 128u) | (us3 < 128u);

        if (own | anyhit) {
            int4 d4 = d_in[e4];
            if (own) {
                ((float4*)out)[e4] =
                    make_float4((float)s4.x, (float)s4.y, (float)s4.z, (float)s4.w);
                ((float4*)(out + AUG))[e4] =
                    make_float4((float)d4.x, (float)d4.y, (float)d4.z, (float)d4.w);
            }
            unsigned ud0 = (unsigned)(d4.x - boff);
            unsigned ud1 = (unsigned)(d4.y - boff);
            unsigned ud2 = (unsigned)(d4.z - boff);
            unsigned ud3 = (unsigned)(d4.w - boff);
            if ((us0 | ud0) < 128u) { unsigned bit = (us0 << 7) | ud0; atomicOr(&bm[bit >> 5], 1u << (bit & 31)); }
            if ((us1 | ud1) < 128u) { unsigned bit = (us1 << 7) | ud1; atomicOr(&bm[bit >> 5], 1u << (bit & 31)); }
            if ((us2 | ud2) < 128u) { unsigned bit = (us2 << 7) | ud2; atomicOr(&bm[bit >> 5], 1u << (bit & 31)); }
            if ((us3 | ud3) < 128u) { unsigned bit = (us3 << 7) | ud3; atomicOr(&bm[bit >> 5], 1u << (bit & 31)); }
        }
    }
    __syncthreads();

    // ---- rank-scan the free bitmap: emit first TOPK free (i,j) ----
    const int lane = t & 31;
    const int wid  = t >> 5;

    unsigned m = ~bm[t];                 // free = not existing
    // Clear the (at most one) diagonal bit in this word: positions p = 129*i.
    int lo = t << 5;
    int i0 = (lo + 128) / 129;
    int p  = i0 * 129;
    if (p < lo + 32) m &= ~(1u << (p - lo));

    int c = __popc(m);

    // Inclusive warp scan of popcounts.
    int v = c;
    #pragma unroll
    for (int off = 1; off < 32; off <<= 1) {
        int x = __shfl_up_sync(0xffffffffu, v, off);
        if (lane >= off) v += x;
    }
    if (lane == 31) wsum[wid] = v;
    __syncthreads();
    if (wid == 0) {
        int x = (lane < 16) ? wsum[lane] : 0;
        #pragma unroll
        for (int off = 1; off < 16; off <<= 1) {
            int y = __shfl_up_sync(0xffffffffu, x, off);
            if (lane >= off) x += y;
        }
        if (lane < 16) wsum[lane] = x;
    }
    __syncthreads();

    int excl = v - c + (wid > 0 ? wsum[wid - 1] : 0);  // exclusive rank over block

    if (excl < TOPK_K && m) {
        unsigned mm = m;
        int r = excl;
        while (mm && r < TOPK_K) {
            int bi = __ffs(mm) - 1;
            mm &= mm - 1;
            int bitpos = lo + bi;
            out[E_EDGES + b * TOPK_K + r]       = (float)(boff + (bitpos >> 7));  // new_src
            out[AUG + E_EDGES + b * TOPK_K + r] = (float)(boff + (bitpos & 127)); // new_dst
            r++;
        }
    }

    if (b == 0 && t == 0 && write_count) out[2 * AUG] = (float)(BQ * TOPK_K);  // added_count
}

extern "C" void kernel_launch(void* const* d_in, const int* in_sizes, int n_in,
                              void* d_out, int out_size) {
    // Locate edge_index by its unique element count (2 * E = 131072, int32).
    const int* ei = nullptr;
    for (int i = 0; i < n_in; i++) {
        if (in_sizes[i] == 2 * E_EDGES) { ei = (const int*)d_in[i]; break; }
    }
    float* out = (float*)d_out;

    fused_kernel<<<BQ, 512>>>(ei, out, (out_size > 2 * AUG) ? 1 : 0);
}

// round 4
// speedup vs baseline: 2.1634x; 2.1634x over previous
#include <cuda_runtime.h>

// EdgeAugmentation, single-launch persistent formulation.
// LayerNorm over a singleton axis => every score == beta => stable top_k picks
// the first TOPK row-major (i,j) per graph that are neither an existing
// same-graph edge nor diagonal. Output buffer is float32.
//
// 64 blocks. Phase 1: block b copies its 1/64 slice of edge_index to the
// output and ORs edge bits into the global per-graph bitmap. Phase 2: ticket
// barrier (monotone counter — replay-safe, no reset). Phase 3: block b
// rank-scans graph b's bitmap for the first 16 free cells, then zeroes its
// slice so the next replay starts from a clean bitmap (device globals are
// zero-initialized at load, so call #1 is clean too).

#define E_EDGES 65536
#define BQ      64
#define TOPK_K  16
#define AUG     (E_EDGES + BQ * TOPK_K)   // 66560 columns in aug_edge_index
#define WORDS   512                        // 128*128 bits / 32

__device__ unsigned g_exist[BQ][WORDS];    // zero-init; restored to zero each run
__device__ unsigned g_bar;                 // monotone ticket counter

__global__ void __launch_bounds__(512, 1)
fused_kernel(const int* __restrict__ ei, float* __restrict__ out, int write_count) {
    const int b = blockIdx.x;
    const int t = threadIdx.x;      // 0..511

    // ---- Phase 1: copy own slice + set existence bits (2 edges/thread) ----
    {
        int e2 = (b << 9) + t;                      // int2 index: b*512 + t
        int2 s2 = ((const int2*)ei)[e2];
        int2 d2 = ((const int2*)(ei + E_EDGES))[e2];
        ((float2*)out)[e2]         = make_float2((float)s2.x, (float)s2.y);
        ((float2*)(out + AUG))[e2] = make_float2((float)d2.x, (float)d2.y);

        int g0 = s2.x >> 7;
        if ((d2.x >> 7) == g0) {
            unsigned bit = ((unsigned)(s2.x & 127) << 7) | (unsigned)(d2.x & 127);
            atomicOr(&g_exist[g0][bit >> 5], 1u << (bit & 31));
        }
        int g1 = s2.y >> 7;
        if ((d2.y >> 7) == g1) {
            unsigned bit = ((unsigned)(s2.y & 127) << 7) | (unsigned)(d2.y & 127);
            atomicOr(&g_exist[g1][bit >> 5], 1u << (bit & 31));
        }
    }

    // ---- Phase 2: grid barrier (ticket-based, monotone across replays) ----
    __syncthreads();
    if (t == 0) {
        __threadfence();
        unsigned ticket = atomicAdd(&g_bar, 1u);
        unsigned target = ((ticket >> 6) + 1u) << 6;   // end of this group of 64
        while (*((volatile unsigned*)&g_bar) < target) { }
        __threadfence();
    }
    __syncthreads();

    // ---- Phase 3: rank-scan graph b's free bitmap; emit first TOPK cells ----
    const int lane = t & 31;
    const int wid  = t >> 5;
    const int boff = b << 7;

    unsigned m = ~g_exist[b][t];           // free = not existing
    g_exist[b][t] = 0u;                    // restore precondition for next run

    // Clear the (at most one) diagonal bit in this word: positions p = 129*i.
    int lo = t << 5;
    int i0 = (lo + 128) / 129;
    int p  = i0 * 129;
    if (p < lo + 32) m &= ~(1u << (p - lo));

    int c = __popc(m);

    // Inclusive warp scan of popcounts.
    int v = c;
    #pragma unroll
    for (int off = 1; off < 32; off <<= 1) {
        int x = __shfl_up_sync(0xffffffffu, v, off);
        if (lane >= off) v += x;
    }
    __shared__ int wsum[16];
    if (lane == 31) wsum[wid] = v;
    __syncthreads();
    if (wid == 0) {
        int x = (lane < 16) ? wsum[lane] : 0;
        #pragma unroll
        for (int off = 1; off < 16; off <<= 1) {
            int y = __shfl_up_sync(0xffffffffu, x, off);
            if (lane >= off) x += y;
        }
        if (lane < 16) wsum[lane] = x;
    }
    __syncthreads();

    int excl = v - c + (wid > 0 ? wsum[wid - 1] : 0);  // exclusive rank over block

    if (excl < TOPK_K && m) {
        unsigned mm = m;
        int r = excl;
        while (mm && r < TOPK_K) {
            int bi = __ffs(mm) - 1;
            mm &= mm - 1;
            int bitpos = lo + bi;
            out[E_EDGES + b * TOPK_K + r]       = (float)(boff + (bitpos >> 7));  // new_src
            out[AUG + E_EDGES + b * TOPK_K + r] = (float)(boff + (bitpos & 127)); // new_dst
            r++;
        }
    }

    if (b == 0 && t == 0 && write_count) out[2 * AUG] = (float)(BQ * TOPK_K);  // added_count
}

extern "C" void kernel_launch(void* const* d_in, const int* in_sizes, int n_in,
                              void* d_out, int out_size) {
    // Locate edge_index by its unique element count (2 * E = 131072, int32).
    const int* ei = nullptr;
    for (int i = 0; i < n_in; i++) {
        if (in_sizes[i] == 2 * E_EDGES) { ei = (const int*)d_in[i]; break; }
    }
    float* out = (float*)d_out;

    fused_kernel<<<BQ, 512>>>(ei, out, (out_size > 2 * AUG) ? 1 : 0);
}

// round 5
// speedup vs baseline: 2.4338x; 1.1250x over previous
#include <cuda_runtime.h>

// EdgeAugmentation, single-launch persistent formulation (v2: no L1-flush fences).
// LayerNorm over a singleton axis => every score == beta => stable top_k picks
// the first TOPK row-major (i,j) per graph that are neither an existing
// same-graph edge nor diagonal. Output buffer is float32.
//
// 64 blocks. Phase 1: block b copies its 1/64 slice of edge_index to the
// output and ORs edge bits into the global per-graph bitmap (relaxed L2
// atomics). Phase 2: grid barrier via atom.release.gpu ticket + ld.acquire.gpu
// spin (the cg::grid_group pattern) -- NO __threadfence, so no CCTL.IVALL /
// L1D flush on the critical path. Phase 3: block b rank-scans graph b's free
// bitmap for the first 16 cells, then zeroes its slice so the next graph
// replay starts clean (device globals are zero-init at load => call #1 clean).

#define E_EDGES 65536
#define BQ      64
#define TOPK_K  16
#define AUG     (E_EDGES + BQ * TOPK_K)   // 66560 columns in aug_edge_index
#define WORDS   512                        // 128*128 bits / 32

__device__ unsigned g_exist[BQ][WORDS];    // zero-init; restored to zero each run
__device__ unsigned g_bar;                 // monotone ticket counter

__device__ __forceinline__ unsigned atom_add_release_gpu(unsigned* p, unsigned v) {
    unsigned old;
    asm volatile("atom.release.gpu.global.add.u32 %0, [%1], %2;"
                 : "=r"(old) : "l"(p), "r"(v) : "memory");
    return old;
}
__device__ __forceinline__ unsigned ld_acquire_gpu(const unsigned* p) {
    unsigned v;
    asm volatile("ld.acquire.gpu.global.u32 %0, [%1];"
                 : "=r"(v) : "l"(p) : "memory");
    return v;
}

__global__ void __launch_bounds__(512, 1)
fused_kernel(const int* __restrict__ ei, float* __restrict__ out, int write_count) {
    const int b = blockIdx.x;
    const int t = threadIdx.x;      // 0..511

    // ---- Phase 1: copy own slice + set existence bits (2 edges/thread) ----
    {
        int e2 = (b << 9) + t;                      // int2 index: b*512 + t
        int2 s2 = ((const int2*)ei)[e2];
        int2 d2 = ((const int2*)(ei + E_EDGES))[e2];
        ((float2*)out)[e2]         = make_float2((float)s2.x, (float)s2.y);
        ((float2*)(out + AUG))[e2] = make_float2((float)d2.x, (float)d2.y);

        int g0 = s2.x >> 7;
        if ((d2.x >> 7) == g0) {
            unsigned bit = ((unsigned)(s2.x & 127) << 7) | (unsigned)(d2.x & 127);
            atomicOr(&g_exist[g0][bit >> 5], 1u << (bit & 31));   // RED (no return)
        }
        int g1 = s2.y >> 7;
        if ((d2.y >> 7) == g1) {
            unsigned bit = ((unsigned)(s2.y & 127) << 7) | (unsigned)(d2.y & 127);
            atomicOr(&g_exist[g1][bit >> 5], 1u << (bit & 31));
        }
    }

    // ---- Phase 2: grid barrier, release/acquire (no L1 flush) ----
    __syncthreads();                                  // CTA-scope hb for all REDs
    if (t == 0) {
        unsigned ticket = atom_add_release_gpu(&g_bar, 1u);
        unsigned target = ((ticket >> 6) + 1u) << 6;  // end of this group of 64
        while (ld_acquire_gpu(&g_bar) < target) { }
    }
    __syncthreads();

    // ---- Phase 3: rank-scan graph b's free bitmap; emit first TOPK cells ----
    const int lane = t & 31;
    const int wid  = t >> 5;
    const int boff = b << 7;

    unsigned m = ~__ldcg(&g_exist[b][t]);   // free = not existing (L2-direct)
    g_exist[b][t] = 0u;                     // restore precondition for next run

    // Clear the (at most one) diagonal bit in this word: positions p = 129*i.
    int lo = t << 5;
    int p  = ((lo + 128) / 129) * 129;
    if (p < lo + 32) m &= ~(1u << (p - lo));

    int c = __popc(m);

    // Inclusive warp scan of popcounts.
    int v = c;
    #pragma unroll
    for (int off = 1; off < 32; off <<= 1) {
        int x = __shfl_up_sync(0xffffffffu, v, off);
        if (lane >= off) v += x;
    }
    __shared__ int wsum[16];
    if (lane == 31) wsum[wid] = v;
    __syncthreads();
    if (wid == 0) {
        int x = (lane < 16) ? wsum[lane] : 0;
        #pragma unroll
        for (int off = 1; off < 16; off <<= 1) {
            int y = __shfl_up_sync(0xffffffffu, x, off);
            if (lane >= off) x += y;
        }
        if (lane < 16) wsum[lane] = x;
    }
    __syncthreads();

    int excl = v - c + (wid > 0 ? wsum[wid - 1] : 0);  // exclusive rank over block

    if (excl < TOPK_K && m) {
        unsigned mm = m;
        int r = excl;
        while (mm && r < TOPK_K) {
            int bi = __ffs(mm) - 1;
            mm &= mm - 1;
            int bitpos = lo + bi;
            out[E_EDGES + b * TOPK_K + r]       = (float)(boff + (bitpos >> 7));  // new_src
            out[AUG + E_EDGES + b * TOPK_K + r] = (float)(boff + (bitpos & 127)); // new_dst
            r++;
        }
    }

    if (b == 0 && t == 0 && write_count) out[2 * AUG] = (float)(BQ * TOPK_K);  // added_count
}

extern "C" void kernel_launch(void* const* d_in, const int* in_sizes, int n_in,
                              void* d_out, int out_size) {
    // Locate edge_index by its unique element count (2 * E = 131072, int32).
    const int* ei = nullptr;
    for (int i = 0; i < n_in; i++) {
        if (in_sizes[i] == 2 * E_EDGES) { ei = (const int*)d_in[i]; break; }
    }
    float* out = (float*)d_out;

    fused_kernel<<<BQ, 512>>>(ei, out, (out_size > 2 * AUG) ? 1 : 0);
}